// round 3
// baseline (speedup 1.0000x reference)
#include <cuda_runtime.h>
#include <cuda_pipeline.h>
#include <math.h>

#define Nn 16
#define Ss 4
#define Cc 128
#define Hh 36
#define Ww 36
#define Uu 8000
#define Rr 4
#define HW (Hh*Ww)
#define NKEY (37*37)   // 1369 bilinear cells (floor index in [-1,35] per axis)
#define UT 8           // u-tile per pipeline stage

// Scratch (device globals — no runtime allocation)
__device__ float  g_coreT[(size_t)Nn*Ss*HW*Cc];   // [n][s][p][c], 42.5 MB
__device__ int    g_offsets[NKEY+1];
__device__ int    g_sortedU[Uu];
__device__ float4 g_wts[Uu];                      // per sorted slot: w00,w01,w10,w11

// ---------------------------------------------------------------------------
// 1) Transpose core [n, s*C, h, w] -> coreT [n, s, p, c]  (channels-last)
// ---------------------------------------------------------------------------
__global__ void transpose_kernel(const float* __restrict__ core) {
    __shared__ float tile[32][33];
    int ns = blockIdx.z;
    int c0 = blockIdx.y * 32;
    int p0 = blockIdx.x * 32;
    int tx = threadIdx.x, ty = threadIdx.y;

    int c = c0 + ty, p = p0 + tx;
    if (p < HW) tile[ty][tx] = core[((size_t)ns*Cc + c)*HW + p];
    __syncthreads();
    int pw = p0 + ty, cw = c0 + tx;
    if (pw < HW) g_coreT[((size_t)ns*HW + pw)*Cc + cw] = tile[tx][ty];
}

// ---------------------------------------------------------------------------
// 2) Single-block binning: histogram -> scan -> scatter (+ weight precompute)
// ---------------------------------------------------------------------------
__global__ void __launch_bounds__(1024, 1)
binsort_kernel(const float* __restrict__ pos) {
    __shared__ int hist[NKEY];     // histogram, later reused as scatter cursor
    __shared__ int wexc[32];       // per-warp exclusive offsets
    __shared__ int sTotal;

    int t    = threadIdx.x;
    int lane = t & 31;
    int warp = t >> 5;

    for (int i = t; i < NKEY; i += 1024) hist[i] = 0;
    __syncthreads();

    // histogram (8 u's per thread); keep keys in registers for scatter phase
    int mykey[(Uu + 1023) / 1024];
    #pragma unroll
    for (int k = 0; k < (Uu + 1023) / 1024; k++) {
        int u = t + k * 1024;
        int key = -1;
        if (u < Uu) {
            float x = ((pos[2*u]   + 1.0f) * (float)Ww - 1.0f) * 0.5f;
            float y = ((pos[2*u+1] + 1.0f) * (float)Hh - 1.0f) * 0.5f;
            int kx = (int)floorf(x); kx = max(-1, min(kx, Ww-1));
            int ky = (int)floorf(y); ky = max(-1, min(ky, Hh-1));
            key = (ky+1)*37 + (kx+1);
            atomicAdd(&hist[key], 1);
        }
        mykey[k] = key;
    }
    __syncthreads();

    // exclusive scan of hist[0..NKEY): 2 elements per thread, 2-level warp scan
    int i0 = 2*t, i1 = 2*t + 1;
    int a = (i0 < NKEY) ? hist[i0] : 0;
    int b = (i1 < NKEY) ? hist[i1] : 0;
    int pairv = a + b;
    int x = pairv;
    #pragma unroll
    for (int d = 1; d < 32; d <<= 1) {
        int y = __shfl_up_sync(0xffffffffu, x, d);
        if (lane >= d) x += y;
    }
    if (lane == 31) wexc[warp] = x;   // warp inclusive total
    __syncthreads();
    if (warp == 0) {
        int v = wexc[lane];
        int sx = v;
        #pragma unroll
        for (int d = 1; d < 32; d <<= 1) {
            int y = __shfl_up_sync(0xffffffffu, sx, d);
            if (lane >= d) sx += y;
        }
        wexc[lane] = sx - v;          // exclusive
        if (lane == 31) sTotal = sx;  // grand total
    }
    __syncthreads();

    int base = (x - pairv) + wexc[warp];   // exclusive offset of i0
    __syncthreads();                       // hist reads done; safe to overwrite
    if (i0 < NKEY) { g_offsets[i0] = base;     hist[i0] = base; }
    if (i1 < NKEY) { g_offsets[i1] = base + a; hist[i1] = base + a; }
    if (t == 0) g_offsets[NKEY] = sTotal;
    __syncthreads();

    // scatter + weight precompute
    #pragma unroll
    for (int k = 0; k < (Uu + 1023) / 1024; k++) {
        int u = t + k * 1024;
        if (mykey[k] >= 0) {
            int p = atomicAdd(&hist[mykey[k]], 1);
            g_sortedU[p] = u;
            float xx = ((pos[2*u]   + 1.0f) * (float)Ww - 1.0f) * 0.5f;
            float yy = ((pos[2*u+1] + 1.0f) * (float)Hh - 1.0f) * 0.5f;
            float wx = xx - floorf(xx);
            float wy = yy - floorf(yy);
            g_wts[p] = make_float4((1.0f-wx)*(1.0f-wy), wx*(1.0f-wy),
                                   (1.0f-wx)*wy,        wx*wy);
        }
    }
}

// ---------------------------------------------------------------------------
// 3) Main: one block per (cell, s). Corners in registers; feature pipelined
//    through double-buffered smem in tiles of UT u's via cp.async.
// ---------------------------------------------------------------------------
__global__ void __launch_bounds__(256, 3)
main_kernel(const float* __restrict__ feature,
            const float* __restrict__ bias,
            float* __restrict__ out)
{
    int cell  = blockIdx.x;
    int s     = blockIdx.y;
    int start = g_offsets[cell];
    int end   = g_offsets[cell+1];
    int cnt   = end - start;
    if (cnt == 0) return;

    int cx = cell % 37 - 1;
    int cy = cell / 37 - 1;
    int x0 = max(cx, 0), x1 = min(cx+1, Ww-1);
    int y0 = max(cy, 0), y1 = min(cy+1, Hh-1);
    int pix0 = y0*Ww + x0;   // w00
    int pix1 = y0*Ww + x1;   // w01
    int pix2 = y1*Ww + x0;   // w10
    int pix3 = y1*Ww + x1;   // w11

    int t   = threadIdx.x;
    int n   = t >> 4;
    int sub = t & 15;

    // One-time corner load: 4 corners x 8 channels into registers
    const float* baseT = g_coreT + ((size_t)(n*Ss + s))*HW*Cc + sub*8;
    float4 cv[4][2];
    {
        const float4* p0 = (const float4*)(baseT + (size_t)pix0*Cc);
        const float4* p1 = (const float4*)(baseT + (size_t)pix1*Cc);
        const float4* p2 = (const float4*)(baseT + (size_t)pix2*Cc);
        const float4* p3 = (const float4*)(baseT + (size_t)pix3*Cc);
        cv[0][0] = p0[0]; cv[0][1] = p0[1];
        cv[1][0] = p1[0]; cv[1][1] = p1[1];
        cv[2][0] = p2[0]; cv[2][1] = p2[1];
        cv[3][0] = p3[0]; cv[3][1] = p3[1];
    }

    __shared__ float4 smF[2][UT*128];   // feature tiles (2 x 16 KB)
    __shared__ float4 smW[2][UT];       // bilinear weights
    __shared__ int    smU[2][UT];       // u indices

    int nTiles = (cnt + UT - 1) / UT;

    auto issue = [&](int tk, int bufi) {
        int tbase = start + tk*UT;
        int tcnt  = min(UT, end - tbase);
        for (int e = t; e < tcnt*128; e += 256) {
            int ul = e >> 7;
            int u  = g_sortedU[tbase + ul];
            const float4* src = (const float4*)feature + (((size_t)(s*Uu + u)) << 7) + (e & 127);
            __pipeline_memcpy_async(&smF[bufi][e], src, 16);
        }
        if (t < tcnt) {
            __pipeline_memcpy_async(&smW[bufi][t], &g_wts[tbase + t], 16);
            __pipeline_memcpy_async(&smU[bufi][t], &g_sortedU[tbase + t], 4);
        }
    };

    issue(0, 0);
    __pipeline_commit();

    for (int tk = 0; tk < nTiles; tk++) {
        int  cur  = tk & 1;
        bool more = (tk + 1 < nTiles);
        if (more) { issue(tk + 1, cur ^ 1); __pipeline_commit(); }
        __pipeline_wait_prior(more ? 1 : 0);
        __syncthreads();

        int tcnt = min(UT, cnt - tk*UT);
        for (int ul = 0; ul < tcnt; ul++) {
            float4 w = smW[cur][ul];
            const float4* fb = &smF[cur][ul*128];

            float acc0 = 0.f, acc1 = 0.f, acc2 = 0.f, acc3 = 0.f;
            #pragma unroll
            for (int j = 0; j < 2; j++) {
                float4 sv;
                sv.x = w.x*cv[0][j].x + w.y*cv[1][j].x + w.z*cv[2][j].x + w.w*cv[3][j].x;
                sv.y = w.x*cv[0][j].y + w.y*cv[1][j].y + w.z*cv[2][j].y + w.w*cv[3][j].y;
                sv.z = w.x*cv[0][j].z + w.y*cv[1][j].z + w.z*cv[2][j].z + w.w*cv[3][j].z;
                sv.w = w.x*cv[0][j].w + w.y*cv[1][j].w + w.z*cv[2][j].w + w.w*cv[3][j].w;

                int fi = sub*2 + j;
                float4 f0 = fb[0*32 + fi];
                float4 f1 = fb[1*32 + fi];
                float4 f2 = fb[2*32 + fi];
                float4 f3 = fb[3*32 + fi];
                acc0 += f0.x*sv.x + f0.y*sv.y + f0.z*sv.z + f0.w*sv.w;
                acc1 += f1.x*sv.x + f1.y*sv.y + f1.z*sv.z + f1.w*sv.w;
                acc2 += f2.x*sv.x + f2.y*sv.y + f2.z*sv.z + f2.w*sv.w;
                acc3 += f3.x*sv.x + f3.y*sv.y + f3.z*sv.z + f3.w*sv.w;
            }

            #pragma unroll
            for (int d = 8; d > 0; d >>= 1) {
                acc0 += __shfl_down_sync(0xffffffffu, acc0, d, 16);
                acc1 += __shfl_down_sync(0xffffffffu, acc1, d, 16);
                acc2 += __shfl_down_sync(0xffffffffu, acc2, d, 16);
                acc3 += __shfl_down_sync(0xffffffffu, acc3, d, 16);
            }

            if (sub == 0) {
                int u = smU[cur][ul];
                float4 bb = *((const float4*)bias + (size_t)(s*Uu + u));
                float4 o  = make_float4(acc0 + bb.x, acc1 + bb.y,
                                        acc2 + bb.z, acc3 + bb.w);
                *((float4*)out + ((size_t)(n*Ss + s))*Uu + u) = o;
            }
        }
        __syncthreads();   // all reads of buffer `cur` done before it is refilled
    }
}

// ---------------------------------------------------------------------------
extern "C" void kernel_launch(void* const* d_in, const int* in_sizes, int n_in,
                              void* d_out, int out_size) {
    const float* core      = (const float*)d_in[0];
    const float* positions = (const float*)d_in[1];
    const float* feature   = (const float*)d_in[2];
    const float* bias      = (const float*)d_in[3];
    float* out = (float*)d_out;

    dim3 tb(32, 32);
    dim3 tg((HW + 31)/32, Cc/32, Nn*Ss);
    transpose_kernel<<<tg, tb>>>(core);

    binsort_kernel<<<1, 1024>>>(positions);

    main_kernel<<<dim3(NKEY, Ss), 256>>>(feature, bias, out);
}

// round 4
// speedup vs baseline: 1.1313x; 1.1313x over previous
#include <cuda_runtime.h>
#include <cuda_pipeline.h>
#include <math.h>

#define Nn 16
#define Ss 4
#define Cc 128
#define Hh 36
#define Ww 36
#define Uu 8000
#define Rr 4
#define HW (Hh*Ww)
#define NKEY (37*37)   // 1369 bilinear cells
#define UT 8           // items (s,u) per pipeline stage

// Scratch (device globals — no runtime allocation)
__device__ float  g_coreT[(size_t)Nn*Ss*HW*Cc];   // [n][s][p][c], 42.5 MB
__device__ int    g_offsets[NKEY+1];
__device__ int    g_sortedU[Uu];
__device__ float4 g_wts[Uu];                      // per sorted slot: w00,w01,w10,w11

// ---------------------------------------------------------------------------
// 1) Transpose core [n, s*C, h, w] -> coreT [n, s, p, c]
//    32c x 32px tile / 256-thread block, XOR-swizzled smem, conflict-free.
// ---------------------------------------------------------------------------
__global__ void __launch_bounds__(256)
transpose_kernel(const float* __restrict__ core) {
    __shared__ float tile[32*32];    // word(c,p) = c*32 + (p ^ c)
    int ns = blockIdx.z;             // n*S + s
    int c0 = blockIdx.y * 32;
    int p0 = blockIdx.x * 32;
    int t  = threadIdx.x;

    // Phase A: vectorized load over px. cl = t>>3 (0..31), q = t&7 (px quad)
    int cl = t >> 3, q = t & 7;
    int p  = p0 + q*4;
    if (p < HW) {
        float4 v = *(const float4*)(core + ((size_t)(ns*Cc + c0 + cl))*HW + p);
        tile[cl*32 + ((q*4+0) ^ cl)] = v.x;
        tile[cl*32 + ((q*4+1) ^ cl)] = v.y;
        tile[cl*32 + ((q*4+2) ^ cl)] = v.z;
        tile[cl*32 + ((q*4+3) ^ cl)] = v.w;
    }
    __syncthreads();

    // Phase B: vectorized store over channels. pl = t>>3, cq = t&7
    int pl = t >> 3, cq = t & 7;
    int pg = p0 + pl;
    if (pg < HW) {
        float4 o;
        o.x = tile[(cq*4+0)*32 + (pl ^ (cq*4+0))];
        o.y = tile[(cq*4+1)*32 + (pl ^ (cq*4+1))];
        o.z = tile[(cq*4+2)*32 + (pl ^ (cq*4+2))];
        o.w = tile[(cq*4+3)*32 + (pl ^ (cq*4+3))];
        *(float4*)(g_coreT + ((size_t)ns*HW + pg)*Cc + c0 + cq*4) = o;
    }
}

// ---------------------------------------------------------------------------
// 2) Single-block binning: histogram -> scan -> scatter (+ weight precompute)
// ---------------------------------------------------------------------------
__global__ void __launch_bounds__(1024, 1)
binsort_kernel(const float* __restrict__ pos) {
    __shared__ int hist[NKEY];
    __shared__ int wexc[32];
    __shared__ int sTotal;

    int t    = threadIdx.x;
    int lane = t & 31;
    int warp = t >> 5;

    for (int i = t; i < NKEY; i += 1024) hist[i] = 0;
    __syncthreads();

    int mykey[(Uu + 1023) / 1024];
    #pragma unroll
    for (int k = 0; k < (Uu + 1023) / 1024; k++) {
        int u = t + k * 1024;
        int key = -1;
        if (u < Uu) {
            float x = ((pos[2*u]   + 1.0f) * (float)Ww - 1.0f) * 0.5f;
            float y = ((pos[2*u+1] + 1.0f) * (float)Hh - 1.0f) * 0.5f;
            int kx = (int)floorf(x); kx = max(-1, min(kx, Ww-1));
            int ky = (int)floorf(y); ky = max(-1, min(ky, Hh-1));
            key = (ky+1)*37 + (kx+1);
            atomicAdd(&hist[key], 1);
        }
        mykey[k] = key;
    }
    __syncthreads();

    int i0 = 2*t, i1 = 2*t + 1;
    int a = (i0 < NKEY) ? hist[i0] : 0;
    int b = (i1 < NKEY) ? hist[i1] : 0;
    int pairv = a + b;
    int x = pairv;
    #pragma unroll
    for (int d = 1; d < 32; d <<= 1) {
        int y = __shfl_up_sync(0xffffffffu, x, d);
        if (lane >= d) x += y;
    }
    if (lane == 31) wexc[warp] = x;
    __syncthreads();
    if (warp == 0) {
        int v = wexc[lane];
        int sx = v;
        #pragma unroll
        for (int d = 1; d < 32; d <<= 1) {
            int y = __shfl_up_sync(0xffffffffu, sx, d);
            if (lane >= d) sx += y;
        }
        wexc[lane] = sx - v;
        if (lane == 31) sTotal = sx;
    }
    __syncthreads();

    int base = (x - pairv) + wexc[warp];
    __syncthreads();
    if (i0 < NKEY) { g_offsets[i0] = base;     hist[i0] = base; }
    if (i1 < NKEY) { g_offsets[i1] = base + a; hist[i1] = base + a; }
    if (t == 0) g_offsets[NKEY] = sTotal;
    __syncthreads();

    #pragma unroll
    for (int k = 0; k < (Uu + 1023) / 1024; k++) {
        int u = t + k * 1024;
        if (mykey[k] >= 0) {
            int p = atomicAdd(&hist[mykey[k]], 1);
            g_sortedU[p] = u;
            float xx = ((pos[2*u]   + 1.0f) * (float)Ww - 1.0f) * 0.5f;
            float yy = ((pos[2*u+1] + 1.0f) * (float)Hh - 1.0f) * 0.5f;
            float wx = xx - floorf(xx);
            float wy = yy - floorf(yy);
            g_wts[p] = make_float4((1.0f-wx)*(1.0f-wy), wx*(1.0f-wy),
                                   (1.0f-wx)*wy,        wx*wy);
        }
    }
}

// ---------------------------------------------------------------------------
// 3) Main: one block per CELL. Work list = 4 s-values x cnt u's flattened,
//    pipelined in UT-item tiles via cp.async double buffer. Corner registers
//    reloaded only on s-change (4x per block, block-uniform).
// ---------------------------------------------------------------------------
__global__ void __launch_bounds__(256, 3)
main_kernel(const float* __restrict__ feature,
            const float* __restrict__ bias,
            float* __restrict__ out)
{
    int cell  = blockIdx.x;
    int start = g_offsets[cell];
    int end   = g_offsets[cell+1];
    int cnt   = end - start;
    if (cnt == 0) return;
    int nItems = Ss * cnt;

    int cx = cell % 37 - 1;
    int cy = cell / 37 - 1;
    int x0 = max(cx, 0), x1 = min(cx+1, Ww-1);
    int y0 = max(cy, 0), y1 = min(cy+1, Hh-1);
    int pix[4] = { y0*Ww + x0, y0*Ww + x1, y1*Ww + x0, y1*Ww + x1 };

    int t   = threadIdx.x;
    int n   = t >> 4;
    int sub = t & 15;

    __shared__ float4 smF[2][UT*128];   // feature tiles (2 x 16 KB)
    __shared__ float4 smW[2][UT];       // bilinear weights
    __shared__ int    smU[2][UT];       // u indices

    int nTiles = (nItems + UT - 1) / UT;

    auto issue = [&](int tk, int bufi) {
        int ibase = tk*UT;
        int tcnt  = min(UT, nItems - ibase);
        for (int e = t; e < tcnt*128; e += 256) {
            int item = ibase + (e >> 7);
            int s = 0, it = item;
            while (it >= cnt) { it -= cnt; s++; }
            int u = g_sortedU[start + it];
            const float4* src = (const float4*)feature
                              + (((size_t)(s*Uu + u)) << 7) + (e & 127);
            __pipeline_memcpy_async(&smF[bufi][e], src, 16);
        }
        if (t < tcnt) {
            int item = ibase + t;
            int it = item; while (it >= cnt) it -= cnt;
            __pipeline_memcpy_async(&smW[bufi][t], &g_wts[start + it], 16);
            __pipeline_memcpy_async(&smU[bufi][t], &g_sortedU[start + it], 4);
        }
    };

    issue(0, 0);
    __pipeline_commit();

    float4 cv[4][2];
    int cur_s = -1;

    for (int tk = 0; tk < nTiles; tk++) {
        int  cur  = tk & 1;
        bool more = (tk + 1 < nTiles);
        if (more) { issue(tk + 1, cur ^ 1); __pipeline_commit(); }
        __pipeline_wait_prior(more ? 1 : 0);
        __syncthreads();

        int tcnt = min(UT, nItems - tk*UT);
        for (int ul = 0; ul < tcnt; ul++) {
            int item = tk*UT + ul;
            int s = 0, it = item;
            while (it >= cnt) { it -= cnt; s++; }

            if (s != cur_s) {       // block-uniform
                cur_s = s;
                const float* baseT = g_coreT
                    + ((size_t)(n*Ss + s))*HW*Cc + sub*8;
                #pragma unroll
                for (int j = 0; j < 4; j++) {
                    const float4* pj = (const float4*)(baseT + (size_t)pix[j]*Cc);
                    cv[j][0] = pj[0];
                    cv[j][1] = pj[1];
                }
            }

            float4 w = smW[cur][ul];
            const float4* fb = &smF[cur][ul*128];

            float acc0 = 0.f, acc1 = 0.f, acc2 = 0.f, acc3 = 0.f;
            #pragma unroll
            for (int j = 0; j < 2; j++) {
                float4 sv;
                sv.x = w.x*cv[0][j].x + w.y*cv[1][j].x + w.z*cv[2][j].x + w.w*cv[3][j].x;
                sv.y = w.x*cv[0][j].y + w.y*cv[1][j].y + w.z*cv[2][j].y + w.w*cv[3][j].y;
                sv.z = w.x*cv[0][j].z + w.y*cv[1][j].z + w.z*cv[2][j].z + w.w*cv[3][j].z;
                sv.w = w.x*cv[0][j].w + w.y*cv[1][j].w + w.z*cv[2][j].w + w.w*cv[3][j].w;

                int fi = sub*2 + j;
                float4 f0 = fb[0*32 + fi];
                float4 f1 = fb[1*32 + fi];
                float4 f2 = fb[2*32 + fi];
                float4 f3 = fb[3*32 + fi];
                acc0 += f0.x*sv.x + f0.y*sv.y + f0.z*sv.z + f0.w*sv.w;
                acc1 += f1.x*sv.x + f1.y*sv.y + f1.z*sv.z + f1.w*sv.w;
                acc2 += f2.x*sv.x + f2.y*sv.y + f2.z*sv.z + f2.w*sv.w;
                acc3 += f3.x*sv.x + f3.y*sv.y + f3.z*sv.z + f3.w*sv.w;
            }

            #pragma unroll
            for (int d = 8; d > 0; d >>= 1) {
                acc0 += __shfl_down_sync(0xffffffffu, acc0, d, 16);
                acc1 += __shfl_down_sync(0xffffffffu, acc1, d, 16);
                acc2 += __shfl_down_sync(0xffffffffu, acc2, d, 16);
                acc3 += __shfl_down_sync(0xffffffffu, acc3, d, 16);
            }

            if (sub == 0) {
                int u = smU[cur][ul];
                float4 bb = *((const float4*)bias + (size_t)(s*Uu + u));
                float4 o  = make_float4(acc0 + bb.x, acc1 + bb.y,
                                        acc2 + bb.z, acc3 + bb.w);
                *((float4*)out + ((size_t)(n*Ss + s))*Uu + u) = o;
            }
        }
        __syncthreads();   // buffer reads done before refill
    }
}

// ---------------------------------------------------------------------------
extern "C" void kernel_launch(void* const* d_in, const int* in_sizes, int n_in,
                              void* d_out, int out_size) {
    const float* core      = (const float*)d_in[0];
    const float* positions = (const float*)d_in[1];
    const float* feature   = (const float*)d_in[2];
    const float* bias      = (const float*)d_in[3];
    float* out = (float*)d_out;

    dim3 tg((HW + 31)/32, Cc/32, Nn*Ss);
    transpose_kernel<<<tg, 256>>>(core);

    binsort_kernel<<<1, 1024>>>(positions);

    main_kernel<<<NKEY, 256>>>(feature, bias, out);
}

// round 6
// speedup vs baseline: 2.0797x; 1.8383x over previous
#include <cuda_runtime.h>
#include <cuda_pipeline.h>
#include <math.h>

#define Nn 16
#define Ss 4
#define Cc 128
#define Hh 36
#define Ww 36
#define Uu 8000
#define Rr 4
#define HW (Hh*Ww)
#define NKEY (37*37)   // 1369 bilinear cells
#define UT 4           // items per pipeline stage
#define SEG 6          // keys per thread in 256-thread scan (256*6 >= 1369)

// Scratch (device globals — no runtime allocation)
__device__ float  g_coreT[(size_t)Nn*Ss*HW*Cc];   // [n][s][p][c], 42.5 MB
__device__ int    g_offsets[NKEY+1];
__device__ int    g_sortedU[Uu];
__device__ float4 g_wts[Uu];                      // per sorted slot: w00,w01,w10,w11

// ---------------------------------------------------------------------------
// Fused kernel: z < Nn*Ss  -> transpose tile
//               z == Nn*Ss -> (block 0,0 only) binsort of positions
// ---------------------------------------------------------------------------
__device__ __forceinline__ int cell_key_w(const float* pos, int u,
                                          float& wx, float& wy) {
    float x = ((pos[2*u]   + 1.0f) * (float)Ww - 1.0f) * 0.5f;
    float y = ((pos[2*u+1] + 1.0f) * (float)Hh - 1.0f) * 0.5f;
    float xf = floorf(x), yf = floorf(y);
    wx = x - xf; wy = y - yf;
    int kx = (int)xf; kx = max(-1, min(kx, Ww-1));
    int ky = (int)yf; ky = max(-1, min(ky, Hh-1));
    return (ky+1)*37 + (kx+1);
}

__global__ void __launch_bounds__(256)
prep_kernel(const float* __restrict__ core, const float* __restrict__ pos) {
    __shared__ float tile[32*32];        // transpose path
    __shared__ int   hist[NKEY];         // binsort path
    __shared__ int   curs[NKEY];
    __shared__ int   wtot[8];

    int t = threadIdx.x;

    if (blockIdx.z == (unsigned)(Nn*Ss)) {
        // ---------------- binsort (single block) ----------------
        if (blockIdx.x != 0 || blockIdx.y != 0) return;

        for (int i = t; i < NKEY; i += 256) hist[i] = 0;
        __syncthreads();

        for (int u = t; u < Uu; u += 256) {
            float wx, wy;
            int key = cell_key_w(pos, u, wx, wy);
            atomicAdd(&hist[key], 1);
        }
        __syncthreads();

        // scan: SEG keys/thread, warp scan of totals, warp0 scan of warp sums
        int lane = t & 31, wid = t >> 5;
        int lv[SEG];
        int run = 0;
        #pragma unroll
        for (int k = 0; k < SEG; k++) {
            int i = t*SEG + k;
            run += (i < NKEY) ? hist[i] : 0;
            lv[k] = run;                       // inclusive within segment
        }
        int tot = run;
        int inc = tot;
        #pragma unroll
        for (int d = 1; d < 32; d <<= 1) {
            int y = __shfl_up_sync(0xffffffffu, inc, d);
            if (lane >= d) inc += y;
        }
        if (lane == 31) wtot[wid] = inc;
        __syncthreads();
        if (t == 0) {
            int s = 0;
            #pragma unroll
            for (int w = 0; w < 8; w++) { int v = wtot[w]; wtot[w] = s; s += v; }
        }
        __syncthreads();
        int exc = wtot[wid] + (inc - tot);     // exclusive offset of segment
        #pragma unroll
        for (int k = 0; k < SEG; k++) {
            int i = t*SEG + k;
            if (i < NKEY) {
                int off = exc + lv[k] - hist[i];   // exclusive for key i
                g_offsets[i] = off;
                curs[i] = off;
            }
        }
        if (t == 0) g_offsets[NKEY] = Uu;
        __syncthreads();

        // scatter + weight precompute
        for (int u = t; u < Uu; u += 256) {
            float wx, wy;
            int key = cell_key_w(pos, u, wx, wy);
            int p = atomicAdd(&curs[key], 1);
            g_sortedU[p] = u;
            g_wts[p] = make_float4((1.0f-wx)*(1.0f-wy), wx*(1.0f-wy),
                                   (1.0f-wx)*wy,        wx*wy);
        }
        return;
    }

    // ---------------- transpose tile ----------------
    int ns = blockIdx.z;
    int c0 = blockIdx.y * 32;
    int p0 = blockIdx.x * 32;

    int cl = t >> 3, q = t & 7;
    int p  = p0 + q*4;
    if (p < HW) {
        float4 v = *(const float4*)(core + ((size_t)(ns*Cc + c0 + cl))*HW + p);
        tile[cl*32 + ((q*4+0) ^ cl)] = v.x;
        tile[cl*32 + ((q*4+1) ^ cl)] = v.y;
        tile[cl*32 + ((q*4+2) ^ cl)] = v.z;
        tile[cl*32 + ((q*4+3) ^ cl)] = v.w;
    }
    __syncthreads();

    int pl = t >> 3, cq = t & 7;
    int pg = p0 + pl;
    if (pg < HW) {
        float4 o;
        o.x = tile[(cq*4+0)*32 + (pl ^ (cq*4+0))];
        o.y = tile[(cq*4+1)*32 + (pl ^ (cq*4+1))];
        o.z = tile[(cq*4+2)*32 + (pl ^ (cq*4+2))];
        o.w = tile[(cq*4+3)*32 + (pl ^ (cq*4+3))];
        *(float4*)(g_coreT + ((size_t)ns*HW + pg)*Cc + c0 + cq*4) = o;
    }
}

// ---------------------------------------------------------------------------
// Main: one block per (cell, s). Corners in registers; feature+weights+bias
// prefetched via double-buffered cp.async — NO global loads in compute loop.
// ---------------------------------------------------------------------------
__global__ void __launch_bounds__(256, 4)
main_kernel(const float* __restrict__ feature,
            const float* __restrict__ bias,
            float* __restrict__ out)
{
    int cell  = blockIdx.x;
    int s     = blockIdx.y;
    int start = g_offsets[cell];
    int end   = g_offsets[cell+1];
    int cnt   = end - start;
    if (cnt == 0) return;

    int cx = cell % 37 - 1;
    int cy = cell / 37 - 1;
    int x0 = max(cx, 0), x1 = min(cx+1, Ww-1);
    int y0 = max(cy, 0), y1 = min(cy+1, Hh-1);
    int pix0 = y0*Ww + x0;   // w00
    int pix1 = y0*Ww + x1;   // w01
    int pix2 = y1*Ww + x0;   // w10
    int pix3 = y1*Ww + x1;   // w11

    int t   = threadIdx.x;
    int n   = t >> 4;
    int sub = t & 15;

    __shared__ float4 smF[2][UT*128];   // feature tiles (2 x 8 KB)
    __shared__ float4 smW[2][UT];       // bilinear weights
    __shared__ float4 smB[2][UT];       // bias
    __shared__ int    smU[2][UT];       // u indices

    int nTiles = (cnt + UT - 1) / UT;

    auto issue = [&](int tk, int bufi) {
        int tbase = start + tk*UT;
        int tcnt  = min(UT, end - tbase);
        #pragma unroll
        for (int e2 = 0; e2 < UT*128; e2 += 256) {
            int e = e2 + t;
            if (e < tcnt*128) {
                int u = g_sortedU[tbase + (e >> 7)];
                const float4* src = (const float4*)feature
                                  + (((size_t)(s*Uu + u)) << 7) + (e & 127);
                __pipeline_memcpy_async(&smF[bufi][e], src, 16);
            }
        }
        if (t < tcnt) {
            int u = g_sortedU[tbase + t];
            __pipeline_memcpy_async(&smW[bufi][t], &g_wts[tbase + t], 16);
            __pipeline_memcpy_async(&smB[bufi][t],
                                    (const float4*)bias + (size_t)(s*Uu + u), 16);
            __pipeline_memcpy_async(&smU[bufi][t], &g_sortedU[tbase + t], 4);
        }
    };

    // One-time corner load (overlaps with first async tile)
    issue(0, 0);
    __pipeline_commit();

    const float* baseT = g_coreT + ((size_t)(n*Ss + s))*HW*Cc + sub*8;
    float4 cv[4][2];
    {
        const float4* p0 = (const float4*)(baseT + (size_t)pix0*Cc);
        const float4* p1 = (const float4*)(baseT + (size_t)pix1*Cc);
        const float4* p2 = (const float4*)(baseT + (size_t)pix2*Cc);
        const float4* p3 = (const float4*)(baseT + (size_t)pix3*Cc);
        cv[0][0] = p0[0]; cv[0][1] = p0[1];
        cv[1][0] = p1[0]; cv[1][1] = p1[1];
        cv[2][0] = p2[0]; cv[2][1] = p2[1];
        cv[3][0] = p3[0]; cv[3][1] = p3[1];
    }

    for (int tk = 0; tk < nTiles; tk++) {
        int  cur  = tk & 1;
        if (tk + 1 < nTiles) {
            issue(tk + 1, cur ^ 1);
            __pipeline_commit();
            __pipeline_wait_prior(1);
        } else {
            __pipeline_wait_prior(0);
        }
        __syncthreads();

        #pragma unroll
        for (int ul = 0; ul < UT; ul++) {
            if (tk*UT + ul >= cnt) break;

            float4 w = smW[cur][ul];
            const float4* fb = &smF[cur][ul*128];

            float acc0 = 0.f, acc1 = 0.f, acc2 = 0.f, acc3 = 0.f;
            #pragma unroll
            for (int j = 0; j < 2; j++) {
                float4 sv;
                sv.x = w.x*cv[0][j].x + w.y*cv[1][j].x + w.z*cv[2][j].x + w.w*cv[3][j].x;
                sv.y = w.x*cv[0][j].y + w.y*cv[1][j].y + w.z*cv[2][j].y + w.w*cv[3][j].y;
                sv.z = w.x*cv[0][j].z + w.y*cv[1][j].z + w.z*cv[2][j].z + w.w*cv[3][j].z;
                sv.w = w.x*cv[0][j].w + w.y*cv[1][j].w + w.z*cv[2][j].w + w.w*cv[3][j].w;

                int fi = sub*2 + j;
                float4 f0 = fb[0*32 + fi];
                float4 f1 = fb[1*32 + fi];
                float4 f2 = fb[2*32 + fi];
                float4 f3 = fb[3*32 + fi];
                acc0 += f0.x*sv.x + f0.y*sv.y + f0.z*sv.z + f0.w*sv.w;
                acc1 += f1.x*sv.x + f1.y*sv.y + f1.z*sv.z + f1.w*sv.w;
                acc2 += f2.x*sv.x + f2.y*sv.y + f2.z*sv.z + f2.w*sv.w;
                acc3 += f3.x*sv.x + f3.y*sv.y + f3.z*sv.z + f3.w*sv.w;
            }

            // 5-shuffle reduce over 16 sub-lanes; lane sub<4 ends with r=sub.
            bool p1b = sub & 1;
            float k01 = p1b ? acc1 : acc0;
            float s01 = p1b ? acc0 : acc1;
            k01 += __shfl_xor_sync(0xffffffffu, s01, 1, 16);
            float k23 = p1b ? acc3 : acc2;
            float s23 = p1b ? acc2 : acc3;
            k23 += __shfl_xor_sync(0xffffffffu, s23, 1, 16);
            bool p2b = sub & 2;
            float vk = p2b ? k23 : k01;
            float vs = p2b ? k01 : k23;
            vk += __shfl_xor_sync(0xffffffffu, vs, 2, 16);
            vk += __shfl_xor_sync(0xffffffffu, vk, 4, 16);
            vk += __shfl_xor_sync(0xffffffffu, vk, 8, 16);

            if (sub < 4) {
                int u = smU[cur][ul];
                float b = ((const float*)&smB[cur][ul])[sub];
                out[(((size_t)(n*Ss + s))*Uu + u)*Rr + sub] = vk + b;
            }
        }
        __syncthreads();   // buffer reads done before refill
    }
}

// ---------------------------------------------------------------------------
extern "C" void kernel_launch(void* const* d_in, const int* in_sizes, int n_in,
                              void* d_out, int out_size) {
    const float* core      = (const float*)d_in[0];
    const float* positions = (const float*)d_in[1];
    const float* feature   = (const float*)d_in[2];
    const float* bias      = (const float*)d_in[3];
    float* out = (float*)d_out;

    dim3 tg((HW + 31)/32, Cc/32, Nn*Ss + 1);   // last z-slice: binsort block
    prep_kernel<<<tg, 256>>>(core, positions);

    main_kernel<<<dim3(NKEY, Ss), 256>>>(feature, bias, out);
}